// round 3
// baseline (speedup 1.0000x reference)
#include <cuda_runtime.h>
#include <cstdint>
#include <cstddef>

#define LEN 128
#define HID 64
#define NB 256
#define NN 2048
#define NROWS (NB*NN)          /* 524288 */
#define TILE_M 128
#define NTILES (NROWS/TILE_M)  /* 4096, 16 tiles per batch */
#define WST 132                /* padded smem row stride (floats) */
#define NEG_FILL -1.0e9f
#define LN_EPS 1e-3f

/* shared memory layout (floats) */
#define SM_W   0
#define SM_X0  (LEN*WST)
#define SM_X1  (SM_X0 + TILE_M*WST)
#define SM_ST  (SM_X1 + TILE_M*WST)
#define SM_FLOATS (SM_ST + TILE_M*8)
#define SMEM_BYTES (SM_FLOATS*4)   /* 206848 B */

__device__ float    g_Wc[LEN*WST];     /* combined W1@W2, tf32-rounded, padded */
__device__ float    g_bc[LEN];         /* combined bias b1@W2 + b2 */
__device__ unsigned g_pool[NB*LEN];    /* per-(batch,channel) max, ordered-uint */
__device__ int      g_mask_u8;

__device__ __forceinline__ unsigned f2o(float f){
  unsigned u = __float_as_uint(f);
  return (u & 0x80000000u) ? ~u : (u | 0x80000000u);
}
__device__ __forceinline__ float o2f(unsigned o){
  unsigned u = (o & 0x80000000u) ? (o & 0x7fffffffu) : ~o;
  return __uint_as_float(u);
}
__device__ __forceinline__ unsigned tf32r(float x){
  unsigned r; asm("cvt.rna.tf32.f32 %0, %1;" : "=r"(r) : "f"(x)); return r;
}
__device__ __forceinline__ void mma8(float* c, const unsigned* a, const unsigned* b){
  asm volatile(
    "mma.sync.aligned.m16n8k8.row.col.f32.tf32.tf32.f32 "
    "{%0,%1,%2,%3}, {%4,%5,%6,%7}, {%8,%9}, {%0,%1,%2,%3};\n"
    : "+f"(c[0]), "+f"(c[1]), "+f"(c[2]), "+f"(c[3])
    : "r"(a[0]), "r"(a[1]), "r"(a[2]), "r"(a[3]), "r"(b[0]), "r"(b[1]));
}
__device__ __forceinline__ void cpa16(float* s, const float* g){
  unsigned sa = (unsigned)__cvta_generic_to_shared(s);
  asm volatile("cp.async.cg.shared.global [%0], [%1], 16;\n" :: "r"(sa), "l"(g));
}

/* ---- detect mask packing (bool-as-u8 vs int32) from data ---- */
__global__ void probe_mask_kernel(const unsigned* __restrict__ mw){
  __shared__ int flag;
  if (threadIdx.x == 0) flag = 0;
  __syncthreads();
  int loc = 0;
  #pragma unroll
  for (int k = 0; k < 4; k++){
    if (mw[threadIdx.x*4 + k] > 1u) loc = 1;   /* u8-packed bools make words >1 */
  }
  if (loc) flag = 1;
  __syncthreads();
  if (threadIdx.x == 0) g_mask_u8 = flag;
}

/* ---- precompute combined weight/bias; init pool ---- */
__global__ void prep_kernel(const float* __restrict__ W1, const float* __restrict__ b1,
                            const float* __restrict__ W2, const float* __restrict__ b2){
  int i = blockIdx.x*blockDim.x + threadIdx.x;
  if (i < LEN*LEN){
    int d = i >> 7, j = i & 127;
    float s = 0.f;
    #pragma unroll
    for (int h = 0; h < HID; h++) s += W1[d*HID + h] * W2[h*LEN + j];
    g_Wc[d*WST + j] = __uint_as_float(tf32r(s));
  } else if (i < LEN*LEN + LEN){
    int j = i - LEN*LEN;
    float s = b2[j];
    #pragma unroll
    for (int h = 0; h < HID; h++) s += b1[h] * W2[h*LEN + j];
    g_bc[j] = s;
  } else if (i < LEN*LEN + LEN + NB*LEN){
    g_pool[i - (LEN*LEN + LEN)] = f2o(NEG_FILL);
  }
}

/* ---- main fused kernel: GEMM(tf32) + bias + LN + ReLU + mask + store + pool-max ---- */
__global__ void __launch_bounds__(256,1)
mlp_kernel(const float* __restrict__ X, const void* __restrict__ maskp,
           const float* __restrict__ gamma, const float* __restrict__ beta,
           float* __restrict__ out)
{
  extern __shared__ float sm[];
  float* Ws    = sm + SM_W;
  float* stats = sm + SM_ST;

  const int tid  = threadIdx.x;
  const int lane = tid & 31;
  const int wid  = tid >> 5;
  const int g    = lane >> 2, tig = lane & 3;
  const int wm   = wid >> 2,  wn  = wid & 3;   /* 2 m-warps x 4 n-warps */

  for (int i = tid; i < LEN*WST; i += 256) Ws[i] = g_Wc[i];

  float gam[8], bet[8], bia[8];
  #pragma unroll
  for (int nt = 0; nt < 4; nt++){
    int c0 = wn*32 + nt*8 + 2*tig;
    gam[2*nt] = gamma[c0]; gam[2*nt+1] = gamma[c0+1];
    bet[2*nt] = beta[c0];  bet[2*nt+1] = beta[c0+1];
    bia[2*nt] = g_bc[c0];  bia[2*nt+1] = g_bc[c0+1];
  }
  const bool mu8 = (g_mask_u8 != 0);
  const unsigned char* m8  = (const unsigned char*)maskp;
  const int*           m32 = (const int*)maskp;

  const int t0 = blockIdx.x, stride = gridDim.x;

  /* prefetch first tile into buf0 */
  if (t0 < NTILES){
    const float* src = X + (size_t)t0 * TILE_M * LEN;
    float* dst = sm + SM_X0;
    for (int c = tid; c < TILE_M*32; c += 256){
      int r = c >> 5, q = c & 31;
      cpa16(dst + r*WST + q*4, src + (size_t)r*LEN + q*4);
    }
  }
  asm volatile("cp.async.commit_group;\n" ::: "memory");

  int cur = 0;
  for (int t = t0; t < NTILES; t += stride){
    const int tn = t + stride;
    if (tn < NTILES){
      const float* src = X + (size_t)tn * TILE_M * LEN;
      float* dst = sm + (cur ? SM_X0 : SM_X1);
      for (int c = tid; c < TILE_M*32; c += 256){
        int r = c >> 5, q = c & 31;
        cpa16(dst + r*WST + q*4, src + (size_t)r*LEN + q*4);
      }
    }
    asm volatile("cp.async.commit_group;\n" ::: "memory");
    asm volatile("cp.async.wait_group 1;\n" ::: "memory");
    __syncthreads();

    float* Xs = sm + (cur ? SM_X1 : SM_X0);

    float acc[4][4][4];
    #pragma unroll
    for (int mt = 0; mt < 4; mt++)
      #pragma unroll
      for (int nt = 0; nt < 4; nt++)
        #pragma unroll
        for (int j = 0; j < 4; j++) acc[mt][nt][j] = 0.f;

    #pragma unroll 2
    for (int kk = 0; kk < 16; kk++){
      const int k0 = kk*8;
      unsigned af[4][4];
      #pragma unroll
      for (int mt = 0; mt < 4; mt++){
        int rb = wm*64 + mt*16;
        af[mt][0] = tf32r(Xs[(rb+g  )*WST + k0+tig  ]);
        af[mt][1] = tf32r(Xs[(rb+g+8)*WST + k0+tig  ]);
        af[mt][2] = tf32r(Xs[(rb+g  )*WST + k0+tig+4]);
        af[mt][3] = tf32r(Xs[(rb+g+8)*WST + k0+tig+4]);
      }
      unsigned bf[4][2];
      #pragma unroll
      for (int nt = 0; nt < 4; nt++){
        int cb = wn*32 + nt*8 + g;
        bf[nt][0] = __float_as_uint(Ws[(k0+tig  )*WST + cb]);
        bf[nt][1] = __float_as_uint(Ws[(k0+tig+4)*WST + cb]);
      }
      #pragma unroll
      for (int mt = 0; mt < 4; mt++)
        #pragma unroll
        for (int nt = 0; nt < 4; nt++)
          mma8(acc[mt][nt], af[mt], bf[nt]);
    }
    __syncthreads();   /* all warps done reading Xs before it becomes staging */

    /* bias + LN partial stats (per-row sum & sumsq) */
    #pragma unroll
    for (int mt = 0; mt < 4; mt++){
      float s0=0.f, q0=0.f, s1=0.f, q1=0.f;
      #pragma unroll
      for (int nt = 0; nt < 4; nt++){
        float* a = acc[mt][nt];
        a[0]+=bia[2*nt]; a[1]+=bia[2*nt+1]; a[2]+=bia[2*nt]; a[3]+=bia[2*nt+1];
        s0 += a[0]+a[1]; q0 += a[0]*a[0]+a[1]*a[1];
        s1 += a[2]+a[3]; q1 += a[2]*a[2]+a[3]*a[3];
      }
      #pragma unroll
      for (int off = 1; off < 4; off <<= 1){
        s0 += __shfl_xor_sync(0xffffffffu, s0, off);
        q0 += __shfl_xor_sync(0xffffffffu, q0, off);
        s1 += __shfl_xor_sync(0xffffffffu, s1, off);
        q1 += __shfl_xor_sync(0xffffffffu, q1, off);
      }
      if (tig == 0){
        int rb = wm*64 + mt*16;
        stats[(rb+g  )*8 + wn]     = s0;
        stats[(rb+g  )*8 + 4 + wn] = q0;
        stats[(rb+g+8)*8 + wn]     = s1;
        stats[(rb+g+8)*8 + 4 + wn] = q1;
      }
    }
    __syncthreads();

    const size_t growbase = (size_t)t * TILE_M;
    #pragma unroll
    for (int mt = 0; mt < 4; mt++){
      int rb = wm*64 + mt*16;
      int rg = rb + g, rg8 = rb + g + 8;
      float su  = stats[rg *8+0]+stats[rg *8+1]+stats[rg *8+2]+stats[rg *8+3];
      float sq  = stats[rg *8+4]+stats[rg *8+5]+stats[rg *8+6]+stats[rg *8+7];
      float su8 = stats[rg8*8+0]+stats[rg8*8+1]+stats[rg8*8+2]+stats[rg8*8+3];
      float sq8 = stats[rg8*8+4]+stats[rg8*8+5]+stats[rg8*8+6]+stats[rg8*8+7];
      float mua  = su  * (1.0f/LEN);
      float mub  = su8 * (1.0f/LEN);
      float rsa  = rsqrtf(fmaxf(sq *(1.0f/LEN) - mua*mua, 0.f) + LN_EPS);
      float rsb  = rsqrtf(fmaxf(sq8*(1.0f/LEN) - mub*mub, 0.f) + LN_EPS);
      bool mka = mu8 ? (m8[growbase+rg ] != 0) : (m32[growbase+rg ] != 0);
      bool mkb = mu8 ? (m8[growbase+rg8] != 0) : (m32[growbase+rg8] != 0);
      #pragma unroll
      for (int nt = 0; nt < 4; nt++){
        int c0 = wn*32 + nt*8 + 2*tig;
        float* a = acc[mt][nt];
        float v0 = (a[0]-mua)*rsa*gam[2*nt]   + bet[2*nt];
        float v1 = (a[1]-mua)*rsa*gam[2*nt+1] + bet[2*nt+1];
        float v2 = (a[2]-mub)*rsb*gam[2*nt]   + bet[2*nt];
        float v3 = (a[3]-mub)*rsb*gam[2*nt+1] + bet[2*nt+1];
        v0 = mka ? fmaxf(v0, 0.f) : NEG_FILL;
        v1 = mka ? fmaxf(v1, 0.f) : NEG_FILL;
        v2 = mkb ? fmaxf(v2, 0.f) : NEG_FILL;
        v3 = mkb ? fmaxf(v3, 0.f) : NEG_FILL;
        *(float2*)&Xs[rg *WST + c0] = make_float2(v0, v1);
        *(float2*)&Xs[rg8*WST + c0] = make_float2(v2, v3);
      }
    }
    __syncthreads();

    /* coalesced store of local half + per-column max into global pool */
    {
      const int c4 = tid & 31;
      const int r0 = tid >> 5;
      const int bidx = t >> 4;   /* 16 tiles per batch */
      float mx0=NEG_FILL, mx1=NEG_FILL, mx2=NEG_FILL, mx3=NEG_FILL;
      float* obase = out + growbase * (2*LEN);
      #pragma unroll
      for (int it = 0; it < 16; it++){
        int r = r0 + it*8;
        float4 v = *(float4*)&Xs[r*WST + c4*4];
        *(float4*)(obase + (size_t)r*(2*LEN) + c4*4) = v;
        mx0 = fmaxf(mx0, v.x); mx1 = fmaxf(mx1, v.y);
        mx2 = fmaxf(mx2, v.z); mx3 = fmaxf(mx3, v.w);
      }
      unsigned* pp = g_pool + bidx*LEN + c4*4;
      atomicMax(pp+0, f2o(mx0));
      atomicMax(pp+1, f2o(mx1));
      atomicMax(pp+2, f2o(mx2));
      atomicMax(pp+3, f2o(mx3));
    }
    __syncthreads();   /* staging buffer free before next prefetch overwrites it */
    cur ^= 1;
  }
}

/* ---- broadcast pooled max into second half of output ---- */
__global__ void broadcast_kernel(float* __restrict__ out){
  const int i   = blockIdx.x*blockDim.x + threadIdx.x;  /* 0 .. NROWS*32-1 */
  const int row = i >> 5;
  const int c4  = i & 31;
  const int b   = row >> 11;   /* N = 2048 */
  uint4 p = *(const uint4*)(g_pool + b*LEN + c4*4);
  float4 v = make_float4(o2f(p.x), o2f(p.y), o2f(p.z), o2f(p.w));
  *(float4*)(out + (size_t)row*(2*LEN) + LEN + c4*4) = v;
}

extern "C" void kernel_launch(void* const* d_in, const int* in_sizes, int n_in,
                              void* d_out, int out_size){
  (void)in_sizes; (void)n_in; (void)out_size;
  const float* X    = (const float*)d_in[0];
  const void*  mask = d_in[1];
  const float* W1   = (const float*)d_in[2];
  const float* b1   = (const float*)d_in[3];
  const float* W2   = (const float*)d_in[4];
  const float* b2   = (const float*)d_in[5];
  const float* gm   = (const float*)d_in[6];
  const float* bt   = (const float*)d_in[7];
  float* out = (float*)d_out;

  cudaFuncSetAttribute(mlp_kernel, cudaFuncAttributeMaxDynamicSharedMemorySize, SMEM_BYTES);

  int dev = 0; cudaGetDevice(&dev);
  int sms = 148;
  cudaDeviceGetAttribute(&sms, cudaDevAttrMultiProcessorCount, dev);
  if (sms <= 0) sms = 148;

  probe_mask_kernel<<<1, 256>>>((const unsigned*)mask);
  prep_kernel<<<(LEN*LEN + LEN + NB*LEN + 255)/256, 256>>>(W1, b1, W2, b2);
  mlp_kernel<<<sms, 256, SMEM_BYTES>>>(X, mask, gm, bt, out);
  broadcast_kernel<<<(NROWS*32)/256, 256>>>(out);
}

// round 4
// speedup vs baseline: 1.4598x; 1.4598x over previous
#include <cuda_runtime.h>
#include <cstdint>
#include <cstddef>

#define LEN 128
#define HID 64
#define NB 256
#define NN 2048
#define NROWS (NB*NN)          /* 524288 */
#define TILE_M 128
#define NTILES (NROWS/TILE_M)  /* 4096, 16 tiles per batch */
#define NEG_FILL -1.0e9f
#define LN_EPS 1e-3f

/* W plane-packed layout: Wp[p][c][j] = W[4j+p][c], p=k%4, j=k/4 */
#define CST 36                 /* col stride (floats), mod32=4, 16B-mult */
#define PST (128*CST + 8)      /* 4616 plane stride, mod32=8, 16B-mult */
#define WP_FLOATS (4*PST)      /* 18464 */
#define XST 132                /* X tile row stride (floats), mod32=4 */
#define XTILE (TILE_M*XST)     /* 16896 */

#define SM_X0 WP_FLOATS
#define SM_X1 (SM_X0 + XTILE)
#define SM_ST (SM_X1 + XTILE)
#define SM_FLOATS (SM_ST + TILE_M*8)
#define SMEM_BYTES (SM_FLOATS*4)   /* 213120 B */

__device__ float    g_Wp[WP_FLOATS];   /* combined W1@W2, tf32-rounded, plane-packed */
__device__ float    g_bc[LEN];         /* combined bias b1@W2 + b2 */
__device__ unsigned g_pool[NB*LEN];    /* per-(batch,channel) max, ordered-uint */
__device__ int      g_mask_u8;

__device__ __forceinline__ unsigned f2o(float f){
  unsigned u = __float_as_uint(f);
  return (u & 0x80000000u) ? ~u : (u | 0x80000000u);
}
__device__ __forceinline__ float o2f(unsigned o){
  unsigned u = (o & 0x80000000u) ? (o & 0x7fffffffu) : ~o;
  return __uint_as_float(u);
}
__device__ __forceinline__ unsigned tf32r(float x){
  unsigned r; asm("cvt.rna.tf32.f32 %0, %1;" : "=r"(r) : "f"(x)); return r;
}
__device__ __forceinline__ void mma8(float* c, const unsigned* a, const unsigned* b){
  asm volatile(
    "mma.sync.aligned.m16n8k8.row.col.f32.tf32.tf32.f32 "
    "{%0,%1,%2,%3}, {%4,%5,%6,%7}, {%8,%9}, {%0,%1,%2,%3};\n"
    : "+f"(c[0]), "+f"(c[1]), "+f"(c[2]), "+f"(c[3])
    : "r"(a[0]), "r"(a[1]), "r"(a[2]), "r"(a[3]), "r"(b[0]), "r"(b[1]));
}
__device__ __forceinline__ void cpa16(float* s, const float* g){
  unsigned sa = (unsigned)__cvta_generic_to_shared(s);
  asm volatile("cp.async.cg.shared.global [%0], [%1], 16;\n" :: "r"(sa), "l"(g));
}

/* ---- prep: combined weight (plane layout) + bias + pool init + mask probe ---- */
__global__ void prep_kernel(const float* __restrict__ W1, const float* __restrict__ b1,
                            const float* __restrict__ W2, const float* __restrict__ b2,
                            const unsigned* __restrict__ mw){
  if (blockIdx.x == 0){
    __shared__ int flag;
    if (threadIdx.x == 0) flag = 0;
    __syncthreads();
    int loc = 0;
    #pragma unroll
    for (int k = 0; k < 4; k++)
      if (mw[threadIdx.x*4 + k] > 1u) loc = 1;   /* u8-packed bools -> words >1 */
    if (loc) flag = 1;
    __syncthreads();
    if (threadIdx.x == 0) g_mask_u8 = flag;
  }
  int i = blockIdx.x*blockDim.x + threadIdx.x;
  if (i < LEN*LEN){
    int k = i >> 7, c = i & 127;
    float s = 0.f;
    #pragma unroll
    for (int h = 0; h < HID; h++) s += W1[k*HID + h] * W2[h*LEN + c];
    g_Wp[(k&3)*PST + c*CST + (k>>2)] = __uint_as_float(tf32r(s));
  } else if (i < LEN*LEN + LEN){
    int c = i - LEN*LEN;
    float s = b2[c];
    #pragma unroll
    for (int h = 0; h < HID; h++) s += b1[h] * W2[h*LEN + c];
    g_bc[c] = s;
  } else if (i < LEN*LEN + LEN + NB*LEN){
    g_pool[i - (LEN*LEN + LEN)] = f2o(NEG_FILL);
  }
}

/* ---- fused GEMM(tf32) + bias + LN + ReLU + mask + direct store + pooled max ---- */
__global__ void __launch_bounds__(512,1)
mlp_kernel(const float* __restrict__ X, const void* __restrict__ maskp,
           const float* __restrict__ gamma, const float* __restrict__ beta,
           float* __restrict__ out)
{
  extern __shared__ float sm[];
  float* Wp    = sm;
  float* stats = sm + SM_ST;

  const int tid  = threadIdx.x;
  const int lane = tid & 31;
  const int wid  = tid >> 5;
  const int g    = lane >> 2, tig = lane & 3;
  const int wm   = wid >> 2,  wn  = wid & 3;   /* 4 m-warps x 4 n-warps */
  const int cbase = wn*32;

  for (int i = tid; i < WP_FLOATS; i += 512) Wp[i] = g_Wp[i];

  float gam[8], bet[8], bia[8];
  #pragma unroll
  for (int nt = 0; nt < 4; nt++){
    int c0 = cbase + nt*8 + 2*tig;
    gam[2*nt] = gamma[c0]; gam[2*nt+1] = gamma[c0+1];
    bet[2*nt] = beta[c0];  bet[2*nt+1] = beta[c0+1];
    bia[2*nt] = g_bc[c0];  bia[2*nt+1] = g_bc[c0+1];
  }
  const bool mu8 = (g_mask_u8 != 0);
  const unsigned char* m8  = (const unsigned char*)maskp;
  const int*           m32 = (const int*)maskp;

  const int per = (NTILES + gridDim.x - 1) / gridDim.x;
  const int tb  = blockIdx.x * per;
  const int te  = (tb + per < NTILES) ? tb + per : NTILES;
  if (tb >= te) return;

  float pm[8];
  #pragma unroll
  for (int i = 0; i < 8; i++) pm[i] = NEG_FILL;

  /* prefetch first tile */
  {
    const float* src = X + (size_t)tb * TILE_M * LEN;
    float* dst = sm + SM_X0;
    #pragma unroll
    for (int c = tid; c < TILE_M*32; c += 512){
      int r = c >> 5, q = c & 31;
      cpa16(dst + r*XST + q*4, src + (size_t)r*LEN + q*4);
    }
  }
  asm volatile("cp.async.commit_group;\n" ::: "memory");

  for (int t = tb; t < te; t++){
    const int cur = (t - tb) & 1;
    if (t + 1 < te){
      const float* src = X + (size_t)(t+1) * TILE_M * LEN;
      float* dst = sm + (cur ? SM_X0 : SM_X1);
      #pragma unroll
      for (int c = tid; c < TILE_M*32; c += 512){
        int r = c >> 5, q = c & 31;
        cpa16(dst + r*XST + q*4, src + (size_t)r*LEN + q*4);
      }
    }
    asm volatile("cp.async.commit_group;\n" ::: "memory");
    asm volatile("cp.async.wait_group 1;\n" ::: "memory");
    __syncthreads();                                  /* (A) cur tile ready */

    const float* Xs = sm + (cur ? SM_X1 : SM_X0);

    float acc[2][4][4];
    #pragma unroll
    for (int mt = 0; mt < 2; mt++)
      #pragma unroll
      for (int nt = 0; nt < 4; nt++)
        #pragma unroll
        for (int j = 0; j < 4; j++) acc[mt][nt][j] = 0.f;

    #pragma unroll
    for (int kk2 = 0; kk2 < 8; kk2++){
      float4 w4[4];
      #pragma unroll
      for (int nt = 0; nt < 4; nt++)
        w4[nt] = *(const float4*)&Wp[tig*PST + (cbase + nt*8 + g)*CST + kk2*4];
      #pragma unroll
      for (int half = 0; half < 2; half++){
        const int k0 = kk2*16 + half*8;
        unsigned af[2][4];
        #pragma unroll
        for (int mt = 0; mt < 2; mt++){
          int rb = wm*32 + mt*16;
          af[mt][0] = __float_as_uint(Xs[(rb+g  )*XST + k0+tig  ]);  /* raw bits: tf32 trunc */
          af[mt][1] = __float_as_uint(Xs[(rb+g+8)*XST + k0+tig  ]);
          af[mt][2] = __float_as_uint(Xs[(rb+g  )*XST + k0+tig+4]);
          af[mt][3] = __float_as_uint(Xs[(rb+g+8)*XST + k0+tig+4]);
        }
        unsigned bf[4][2];
        #pragma unroll
        for (int nt = 0; nt < 4; nt++){
          bf[nt][0] = half ? __float_as_uint(w4[nt].z) : __float_as_uint(w4[nt].x);
          bf[nt][1] = half ? __float_as_uint(w4[nt].w) : __float_as_uint(w4[nt].y);
        }
        #pragma unroll
        for (int mt = 0; mt < 2; mt++)
          #pragma unroll
          for (int nt = 0; nt < 4; nt++)
            mma8(acc[mt][nt], af[mt], bf[nt]);
      }
    }

    /* bias + LN partial stats */
    #pragma unroll
    for (int mt = 0; mt < 2; mt++){
      float s0=0.f, q0=0.f, s1=0.f, q1=0.f;
      #pragma unroll
      for (int nt = 0; nt < 4; nt++){
        float* a = acc[mt][nt];
        a[0]+=bia[2*nt]; a[1]+=bia[2*nt+1]; a[2]+=bia[2*nt]; a[3]+=bia[2*nt+1];
        s0 += a[0]+a[1]; q0 += a[0]*a[0]+a[1]*a[1];
        s1 += a[2]+a[3]; q1 += a[2]*a[2]+a[3]*a[3];
      }
      #pragma unroll
      for (int off = 1; off < 4; off <<= 1){
        s0 += __shfl_xor_sync(0xffffffffu, s0, off);
        q0 += __shfl_xor_sync(0xffffffffu, q0, off);
        s1 += __shfl_xor_sync(0xffffffffu, s1, off);
        q1 += __shfl_xor_sync(0xffffffffu, q1, off);
      }
      if (tig == 0){
        int rb = wm*32 + mt*16;
        stats[(rb+g  )*8 + wn]     = s0;
        stats[(rb+g  )*8 + 4 + wn] = q0;
        stats[(rb+g+8)*8 + wn]     = s1;
        stats[(rb+g+8)*8 + 4 + wn] = q1;
      }
    }
    __syncthreads();                                  /* (B) stats ready; buffers safe */

    const size_t growbase = (size_t)t * TILE_M;
    #pragma unroll
    for (int mt = 0; mt < 2; mt++){
      const int rb = wm*32 + mt*16;
      const int rg = rb + g, rg8 = rb + g + 8;
      float4 su4a = *(const float4*)&stats[rg *8];
      float4 sq4a = *(const float4*)&stats[rg *8 + 4];
      float4 su4b = *(const float4*)&stats[rg8*8];
      float4 sq4b = *(const float4*)&stats[rg8*8 + 4];
      float sua = su4a.x+su4a.y+su4a.z+su4a.w, sqa = sq4a.x+sq4a.y+sq4a.z+sq4a.w;
      float sub = su4b.x+su4b.y+su4b.z+su4b.w, sqb = sq4b.x+sq4b.y+sq4b.z+sq4b.w;
      float mua = sua * (1.0f/LEN), mub = sub * (1.0f/LEN);
      float rsa = rsqrtf(fmaxf(sqa*(1.0f/LEN) - mua*mua, 0.f) + LN_EPS);
      float rsb = rsqrtf(fmaxf(sqb*(1.0f/LEN) - mub*mub, 0.f) + LN_EPS);
      bool mka = mu8 ? (m8[growbase+rg ] != 0) : (m32[growbase+rg ] != 0);
      bool mkb = mu8 ? (m8[growbase+rg8] != 0) : (m32[growbase+rg8] != 0);
      float* orowa = out + (growbase + rg ) * (2*LEN);
      float* orowb = out + (growbase + rg8) * (2*LEN);
      #pragma unroll
      for (int nt = 0; nt < 4; nt++){
        const int c0 = cbase + nt*8 + 2*tig;
        float* a = acc[mt][nt];
        float v0 = (a[0]-mua)*rsa*gam[2*nt]   + bet[2*nt];
        float v1 = (a[1]-mua)*rsa*gam[2*nt+1] + bet[2*nt+1];
        float v2 = (a[2]-mub)*rsb*gam[2*nt]   + bet[2*nt];
        float v3 = (a[3]-mub)*rsb*gam[2*nt+1] + bet[2*nt+1];
        v0 = mka ? fmaxf(v0, 0.f) : NEG_FILL;
        v1 = mka ? fmaxf(v1, 0.f) : NEG_FILL;
        v2 = mkb ? fmaxf(v2, 0.f) : NEG_FILL;
        v3 = mkb ? fmaxf(v3, 0.f) : NEG_FILL;
        __stcs((float2*)(orowa + c0), make_float2(v0, v1));
        __stcs((float2*)(orowb + c0), make_float2(v2, v3));
        pm[2*nt]   = fmaxf(pm[2*nt],   fmaxf(v0, v2));
        pm[2*nt+1] = fmaxf(pm[2*nt+1], fmaxf(v1, v3));
      }
    }

    /* flush pool at batch boundary (batch = 16 tiles, aligned) */
    if (t == te-1 || ((t+1) >> 4) != (t >> 4)){
      #pragma unroll
      for (int i = 0; i < 8; i++){
        pm[i] = fmaxf(pm[i], __shfl_xor_sync(0xffffffffu, pm[i], 4));
        pm[i] = fmaxf(pm[i], __shfl_xor_sync(0xffffffffu, pm[i], 8));
        pm[i] = fmaxf(pm[i], __shfl_xor_sync(0xffffffffu, pm[i], 16));
      }
      if (lane < 4){   /* g==0 lanes: tig = lane */
        unsigned* pp = g_pool + (t >> 4)*LEN;
        #pragma unroll
        for (int nt = 0; nt < 4; nt++){
          int c0 = cbase + nt*8 + 2*lane;
          atomicMax(pp + c0,     f2o(pm[2*nt]));
          atomicMax(pp + c0 + 1, f2o(pm[2*nt+1]));
        }
      }
      #pragma unroll
      for (int i = 0; i < 8; i++) pm[i] = NEG_FILL;
    }
  }
}

/* ---- broadcast pooled max into second half of output ---- */
__global__ void __launch_bounds__(256,8)
broadcast_kernel(float* __restrict__ out){
  const int b   = blockIdx.x >> 3;          /* batch */
  const int rch = (blockIdx.x & 7) * 256;   /* row chunk within batch */
  const int c4  = threadIdx.x & 31;
  const int w   = threadIdx.x >> 5;
  uint4 p = *(const uint4*)(g_pool + b*LEN + c4*4);
  float4 v = make_float4(o2f(p.x), o2f(p.y), o2f(p.z), o2f(p.w));
  float* base = out + ((size_t)b*NN + rch) * (2*LEN) + LEN + c4*4;
  #pragma unroll
  for (int it = 0; it < 32; it++)
    __stcs((float4*)(base + (size_t)(w + it*8) * (2*LEN)), v);
}

extern "C" void kernel_launch(void* const* d_in, const int* in_sizes, int n_in,
                              void* d_out, int out_size){
  (void)in_sizes; (void)n_in; (void)out_size;
  const float* X    = (const float*)d_in[0];
  const void*  mask = d_in[1];
  const float* W1   = (const float*)d_in[2];
  const float* b1   = (const float*)d_in[3];
  const float* W2   = (const float*)d_in[4];
  const float* b2   = (const float*)d_in[5];
  const float* gm   = (const float*)d_in[6];
  const float* bt   = (const float*)d_in[7];
  float* out = (float*)d_out;

  cudaFuncSetAttribute(mlp_kernel, cudaFuncAttributeMaxDynamicSharedMemorySize, SMEM_BYTES);

  int dev = 0; cudaGetDevice(&dev);
  int sms = 148;
  cudaDeviceGetAttribute(&sms, cudaDevAttrMultiProcessorCount, dev);
  if (sms <= 0) sms = 148;

  prep_kernel<<<(LEN*LEN + LEN + NB*LEN + 255)/256, 256>>>(W1, b1, W2, b2,
                                                           (const unsigned*)mask);
  mlp_kernel<<<sms, 512, SMEM_BYTES>>>(X, mask, gm, bt, out);
  broadcast_kernel<<<NB*8, 256>>>(out);
}